// round 17
// baseline (speedup 1.0000x reference)
#include <cuda_runtime.h>
#include <math.h>
#include <stdint.h>

// Problem constants (fixed shapes)
#define T_TOK 2048
#define DIM   2048
#define NE    16
#define NI    1024
#define SIH   2048
#define TOPK  4
#define CAP   2048

// ---------------- scratch (device globals; no allocation allowed) ----------------
__device__ int   d_top_idx[T_TOK * TOPK];
__device__ float d_top_w[T_TOK * TOPK];
__device__ int   d_pos[T_TOK * TOPK];
__device__ int   d_counts[NE];
__device__ int   d_tok[NE * CAP];
__device__ float d_xt[(size_t)T_TOK * DIM];                    // tf32-rounded x
__device__ float d_wgu_t[(size_t)NE * (2 * NI) * DIM];         // [E][2I interleaved g,u][D]
__device__ float d_wdn_t[(size_t)NE * DIM * NI];               // [E][D][I]  tf32
__device__ float d_wsgu_t[(size_t)(2 * SIH) * DIM];            // [2SI interleaved][D]
__device__ float d_wsd_t[(size_t)DIM * SIH];                   // [D][SI]    tf32
__device__ float d_gu[(size_t)NE * CAP * 2048];                // fp32 y scratch
__device__ float d_acts[(size_t)T_TOK * SIH];                  // tf32-rounded shared act
__device__ float d_acte[(size_t)NE * CAP * NI];                // tf32-rounded expert act

__device__ __forceinline__ float silu_f(float v) { return v / (1.0f + expf(-v)); }

__device__ __forceinline__ float to_tf32(float a) {
    uint32_t u;
    asm("cvt.rna.tf32.f32 %0, %1;" : "=r"(u) : "f"(a));
    return __uint_as_float(u);
}

__device__ __forceinline__ uint32_t s2u(const void* p) {
    uint32_t a;
    asm("{ .reg .u64 t; cvta.to.shared.u64 t, %1; cvt.u32.u64 %0, t; }" : "=r"(a) : "l"(p));
    return a;
}

#define CP16(sm, gp) asm volatile("cp.async.cg.shared.global [%0], [%1], 16;" :: "r"(sm), "l"(gp))
#define CP_COMMIT()  asm volatile("cp.async.commit_group;" ::: "memory")
#define CP_WAIT1()   asm volatile("cp.async.wait_group 1;" ::: "memory")

#define LDSM4(r, a) \
    asm volatile("ldmatrix.sync.aligned.m8n8.x4.shared.b16 {%0,%1,%2,%3}, [%4];" \
        : "=r"((r)[0]), "=r"((r)[1]), "=r"((r)[2]), "=r"((r)[3]) : "r"(a))

#define MMA_TF32(c, a, b0, b1) \
    asm volatile("mma.sync.aligned.m16n8k8.row.col.f32.tf32.tf32.f32 " \
        "{%0,%1,%2,%3}, {%4,%5,%6,%7}, {%8,%9}, {%0,%1,%2,%3};" \
        : "+f"((c)[0]), "+f"((c)[1]), "+f"((c)[2]), "+f"((c)[3]) \
        : "r"((a)[0]), "r"((a)[1]), "r"((a)[2]), "r"((a)[3]), "r"(b0), "r"(b1))

// ---------------- router ----------------
__global__ void router_kernel(const float* __restrict__ x,
                              const float* __restrict__ gw,
                              const float* __restrict__ gb,
                              int* __restrict__ tidx, float* __restrict__ tw) {
    const int t = blockIdx.x;
    const int tid = threadIdx.x;
    const float* xr = x + (size_t)t * DIM;
    float acc[NE];
#pragma unroll
    for (int e = 0; e < NE; ++e) acc[e] = 0.0f;
    for (int d = tid; d < DIM; d += 128) {
        float xv = xr[d];
#pragma unroll
        for (int e = 0; e < NE; ++e) acc[e] += xv * gw[e * DIM + d];
    }
    __shared__ float red[NE][128];
#pragma unroll
    for (int e = 0; e < NE; ++e) red[e][tid] = acc[e];
    __syncthreads();
    for (int s = 64; s > 0; s >>= 1) {
        if (tid < s) {
#pragma unroll
            for (int e = 0; e < NE; ++e) red[e][tid] += red[e][tid + s];
        }
        __syncthreads();
    }
    if (tid == 0) {
        float logit[NE], p[NE];
        float mx = -1e30f;
#pragma unroll
        for (int e = 0; e < NE; ++e) { logit[e] = red[e][0]; mx = fmaxf(mx, logit[e]); }
        float sum = 0.0f;
#pragma unroll
        for (int e = 0; e < NE; ++e) { p[e] = expf(logit[e] - mx); sum += p[e]; }
        float inv = 1.0f / sum;
#pragma unroll
        for (int e = 0; e < NE; ++e) p[e] *= inv;
        float bmin = gb[0];
#pragma unroll
        for (int e = 1; e < NE; ++e) bmin = fminf(bmin, gb[e]);
        float biased[NE];
#pragma unroll
        for (int e = 0; e < NE; ++e) biased[e] = p[e] + (gb[e] - bmin);
        int sel[TOPK];
        float wsum = 0.0f;
#pragma unroll
        for (int k = 0; k < TOPK; ++k) {
            int bi = 0; float bv = -1e30f;
#pragma unroll
            for (int e = 0; e < NE; ++e)
                if (biased[e] > bv) { bv = biased[e]; bi = e; }
            sel[k] = bi;
            wsum += p[bi];
            biased[bi] = -1e30f;
        }
        float invw = 1.0f / wsum;
#pragma unroll
        for (int k = 0; k < TOPK; ++k) {
            tidx[t * TOPK + k] = sel[k];
            tw[t * TOPK + k] = p[sel[k]] * invw;
        }
    }
}

// ---------------- deterministic routing build + inverse map ----------------
__global__ void routing_build(const int* __restrict__ tidx,
                              int* __restrict__ tok,
                              int* __restrict__ posOut,
                              int* __restrict__ counts) {
    const int e = blockIdx.x;
    const int tid = threadIdx.x;
    const int lane = tid & 31, wid = tid >> 5;
    __shared__ int wcnts[8];
    int cnt = 0;
    for (int base = 0; base < T_TOK * TOPK; base += 256) {
        int i = base + tid;
        bool m = (tidx[i] == e);
        unsigned ball = __ballot_sync(0xffffffffu, m);
        if (lane == 0) wcnts[wid] = __popc(ball);
        __syncthreads();
        int woff = 0, tot = 0;
#pragma unroll
        for (int w = 0; w < 8; ++w) { int c = wcnts[w]; if (w < wid) woff += c; tot += c; }
        if (m) {
            int pos = cnt + woff + __popc(ball & ((1u << lane) - 1u));
            tok[e * CAP + pos] = i >> 2;
            posOut[i] = pos;
        }
        cnt += tot;
        __syncthreads();
    }
    if (tid == 0) counts[e] = cnt;
}

// ---------------- prep: tf32-round x ----------------
__global__ void round_x_kernel(const float* __restrict__ x, float* __restrict__ xt) {
    size_t gi = ((size_t)blockIdx.x * 256 + threadIdx.x) * 4;
    float4 v = *(const float4*)(x + gi);
    v.x = to_tf32(v.x); v.y = to_tf32(v.y); v.z = to_tf32(v.z); v.w = to_tf32(v.w);
    *(float4*)(xt + gi) = v;
}

// ---------------- prep: fast transpose W[R][C] -> O[perm(C)][R], tf32-rounded ---
// 64x64 tiles, float4 loads, 32B-per-row transposed stores.
// H > 0: gate/up interleave  c < H -> 2c ; c >= H -> 2(c-H)+1.
__global__ void transpose_tf32_v2(const float* __restrict__ Wb, long long sWe,
                                  float* __restrict__ Ob, long long sOe,
                                  int R, int C, int H) {
    const float* W = Wb + (size_t)blockIdx.z * sWe;
    float* O = Ob + (size_t)blockIdx.z * sOe;
    const int r0 = blockIdx.y * 64;
    const int c0 = blockIdx.x * 64;
    __shared__ float s[64][65];
    const int tid = threadIdx.x;
    const int cx = (tid & 15) * 4;
    const int ry = tid >> 4;          // 0..15
#pragma unroll
    for (int i = 0; i < 4; ++i) {
        int row = ry + 16 * i;
        float4 v = *(const float4*)(W + (size_t)(r0 + row) * C + c0 + cx);
        s[row][cx] = v.x; s[row][cx + 1] = v.y; s[row][cx + 2] = v.z; s[row][cx + 3] = v.w;
    }
    __syncthreads();
    const int c = tid & 63;
    const int rb = tid >> 6;          // 0..3
    const int cc = c0 + c;
    const int p = H ? ((cc < H) ? 2 * cc : 2 * (cc - H) + 1) : cc;
    float* orow = O + (size_t)p * R + r0;
#pragma unroll
    for (int pass = 0; pass < 2; ++pass) {
        int rs = (rb + 4 * pass) * 8;
        float4 a, b;
        a.x = to_tf32(s[rs + 0][c]); a.y = to_tf32(s[rs + 1][c]);
        a.z = to_tf32(s[rs + 2][c]); a.w = to_tf32(s[rs + 3][c]);
        b.x = to_tf32(s[rs + 4][c]); b.y = to_tf32(s[rs + 5][c]);
        b.z = to_tf32(s[rs + 6][c]); b.w = to_tf32(s[rs + 7][c]);
        *(float4*)(orow + rs) = a;
        *(float4*)(orow + rs + 4) = b;
    }
}

// ---------------- final combine ----------------
__global__ void combine_kernel(const float* __restrict__ y,
                               const int* __restrict__ tidx,
                               const int* __restrict__ posArr,
                               const float* __restrict__ tw,
                               float* __restrict__ out) {
    const int b = blockIdx.x;
    const int t = b >> 1;
    const int half = b & 1;
    const int j = half * 1024 + threadIdx.x * 4;
    float4 o = *(const float4*)(out + (size_t)t * DIM + j);
#pragma unroll
    for (int k = 0; k < TOPK; ++k) {
        int e = tidx[t * TOPK + k];
        int p = posArr[t * TOPK + k];
        float w = tw[t * TOPK + k];
        const float4 yv = *(const float4*)(y + ((size_t)e * CAP + p) * DIM + j);
        o.x += w * yv.x; o.y += w * yv.y; o.z += w * yv.z; o.w += w * yv.w;
    }
    *(float4*)(out + (size_t)t * DIM + j) = o;
}

// ============================================================================
// tf32 mma.sync GEMM core: BM=128, BN=128, BK=32, 3-stage cp.async, ldmatrix.
// A [rows][K] (optionally gathered rows), B [N][K].  Two epilogues:
//   GLU=false: plain fp32 store to C [rows][ldc]
//   GLU=true : B columns are interleaved (g,u); writes to_tf32(silu(g)*u)
//              to Act [rows][ldact] (ldact = N/2), rows guarded by M.
// ============================================================================
#define GSMEM_BYTES (3 * 32768)

template <bool GATHER, bool GLU>
__global__ __launch_bounds__(256, 1)
void mma_gemm(const float* __restrict__ Ab, long long sAe, int lda,
              const float* __restrict__ Bb, long long sBe, int ldb,
              float* __restrict__ Cb, long long sCe, int ldc,
              const int* __restrict__ counts, int Mfull, int KT,
              const int* __restrict__ tokBase) {
    const int e = blockIdx.z;
    const int M = counts ? counts[e] : Mfull;
    const int m0 = blockIdx.y * 128;
    if (m0 >= M) return;
    const int n0 = blockIdx.x * 128;

    extern __shared__ char dynsmem[];
    const uint32_t sbase = s2u(dynsmem);

    const float* A = Ab + (size_t)e * sAe;
    const float* B = Bb + (size_t)e * sBe;
    float* C = Cb + (size_t)e * sCe;

    const int tid = threadIdx.x;
    const int lane = tid & 31;
    const int wid = tid >> 5;
    const int wm = wid & 1;        // 2 M-halves of 64
    const int wn = wid >> 1;       // 4 N-quarters of 32

    // ---- cp.async geometry: thread owns one row (tid>>1), half (tid&1) ----
    const int rl = tid >> 1;               // 0..127
    const int halfsel = tid & 1;
    int gr = m0 + rl;
    int grc = (gr < M) ? gr : (M - 1);
    const int src = GATHER ? tokBase[e * CAP + grc] : grc;
    const float* aptr = A + (size_t)src * lda + halfsel * 16;
    const float* bptr = B + (size_t)(n0 + rl) * ldb + halfsel * 16;
    uint32_t sw[4];
#pragma unroll
    for (int j = 0; j < 4; ++j) {
        int kc = halfsel * 4 + j;
        sw[j] = (uint32_t)(((kc ^ (rl & 7)) << 4));
    }
    const uint32_t rowOff = (uint32_t)rl * 128u;

    // ---- ldmatrix geometry ----
    const uint32_t l7 = (uint32_t)(lane & 7);
    const uint32_t abit = (uint32_t)(lane >> 4);          // A: chunk select
    const uint32_t bbit = (uint32_t)((lane >> 3) & 1);    // B: chunk select
    const int ar = (lane & 7) + ((lane >> 3) & 1) * 8;
    const int br = (lane & 7) + (lane >> 4) * 8;
    uint32_t aOff[4], bOff[2];
#pragma unroll
    for (int mt = 0; mt < 4; ++mt)
        aOff[mt] = (uint32_t)((wm * 64 + mt * 16 + ar) * 128);
#pragma unroll
    for (int nt2 = 0; nt2 < 2; ++nt2)
        bOff[nt2] = (uint32_t)((wn * 32 + nt2 * 16 + br) * 128);

    float acc[4][4][4];
#pragma unroll
    for (int i = 0; i < 4; ++i)
#pragma unroll
        for (int j = 0; j < 4; ++j)
#pragma unroll
            for (int q = 0; q < 4; ++q) acc[i][j][q] = 0.0f;

    // ---- stage loader ----
    auto load_stage = [&](int s, int kt) {
        const uint32_t as = sbase + (uint32_t)s * 32768u + rowOff;
        const uint32_t bs = as + 16384u;
        const float* ap = aptr + (size_t)kt * 32;
        const float* bp = bptr + (size_t)kt * 32;
#pragma unroll
        for (int j = 0; j < 4; ++j) {
            CP16(as + sw[j], ap + j * 4);
            CP16(bs + sw[j], bp + j * 4);
        }
    };

    // prologue: stages 0,1
    load_stage(0, 0); CP_COMMIT();
    if (KT > 1) load_stage(1, 1);
    CP_COMMIT();
    CP_WAIT1();
    __syncthreads();

    int cur = 0;
    for (int kt = 0; kt < KT; ++kt) {
        if (kt + 2 < KT) load_stage((kt + 2) % 3, kt + 2);
        CP_COMMIT();

        const uint32_t As0 = sbase + (uint32_t)cur * 32768u;
        const uint32_t Bs0 = As0 + 16384u;
#pragma unroll
        for (int s8 = 0; s8 < 4; ++s8) {
            uint32_t a[4][4];
            uint32_t b[2][4];
            const uint32_t ach = (((uint32_t)(s8 * 2) + abit) ^ l7) << 4;
            const uint32_t bch = (((uint32_t)(s8 * 2) + bbit) ^ l7) << 4;
#pragma unroll
            for (int mt = 0; mt < 4; ++mt) LDSM4(a[mt], As0 + aOff[mt] + ach);
#pragma unroll
            for (int nt2 = 0; nt2 < 2; ++nt2) LDSM4(b[nt2], Bs0 + bOff[nt2] + bch);
#pragma unroll
            for (int mt = 0; mt < 4; ++mt) {
#pragma unroll
                for (int nt = 0; nt < 4; ++nt) {
                    const uint32_t b0 = b[nt >> 1][(nt & 1) * 2 + 0];
                    const uint32_t b1 = b[nt >> 1][(nt & 1) * 2 + 1];
                    MMA_TF32(acc[mt][nt], a[mt], b0, b1);
                }
            }
        }
        CP_WAIT1();
        __syncthreads();
        cur = (cur + 1) % 3;
    }

    if (GLU) {
        // B cols interleaved (g,u): q0/q1 = (g_j,u_j) @ row, q2/q3 @ row+8.
        // ldc here is the act row width (= N/2).
        const int crow = m0 + wm * 64 + (lane >> 2);
        const int j0 = ((n0 + wn * 32) >> 1) + (lane & 3);
#pragma unroll
        for (int mt = 0; mt < 4; ++mt) {
#pragma unroll
            for (int nt = 0; nt < 4; ++nt) {
                int r = crow + mt * 16;
                int j = j0 + nt * 4;
                if (r < M)
                    C[(size_t)r * ldc + j] =
                        to_tf32(silu_f(acc[mt][nt][0]) * acc[mt][nt][1]);
                if (r + 8 < M)
                    C[(size_t)(r + 8) * ldc + j] =
                        to_tf32(silu_f(acc[mt][nt][2]) * acc[mt][nt][3]);
            }
        }
    } else {
        const int crow = m0 + wm * 64 + (lane >> 2);
        const int ccol = n0 + wn * 32 + (lane & 3) * 2;
#pragma unroll
        for (int mt = 0; mt < 4; ++mt) {
#pragma unroll
            for (int nt = 0; nt < 4; ++nt) {
                float* cp = C + (size_t)(crow + mt * 16) * ldc + ccol + nt * 8;
                *(float2*)cp = make_float2(acc[mt][nt][0], acc[mt][nt][1]);
                *(float2*)(cp + (size_t)8 * ldc) = make_float2(acc[mt][nt][2], acc[mt][nt][3]);
            }
        }
    }
}

// ---------------- launch ----------------
extern "C" void kernel_launch(void* const* d_in, const int* in_sizes, int n_in,
                              void* d_out, int out_size) {
    const float* x    = (const float*)d_in[0];
    const float* gw   = (const float*)d_in[1];
    const float* gb   = (const float*)d_in[2];
    const float* wgu  = (const float*)d_in[3];   // [E, D, 2I]
    const float* wdn  = (const float*)d_in[4];   // [E, I, D]
    const float* wsgu = (const float*)d_in[5];   // [D, 2*SI]
    const float* wsd  = (const float*)d_in[6];   // [SI, D]
    float* out = (float*)d_out;

    void* p;
    cudaGetSymbolAddress(&p, d_gu);      float* gu   = (float*)p;
    cudaGetSymbolAddress(&p, d_tok);     int*   tok  = (int*)p;
    cudaGetSymbolAddress(&p, d_counts);  int*   cnt  = (int*)p;
    cudaGetSymbolAddress(&p, d_top_idx); int*   ti   = (int*)p;
    cudaGetSymbolAddress(&p, d_top_w);   float* tw   = (float*)p;
    cudaGetSymbolAddress(&p, d_pos);     int*   pos  = (int*)p;
    cudaGetSymbolAddress(&p, d_xt);      float* xt   = (float*)p;
    cudaGetSymbolAddress(&p, d_wgu_t);   float* wguT = (float*)p;
    cudaGetSymbolAddress(&p, d_wdn_t);   float* wdnT = (float*)p;
    cudaGetSymbolAddress(&p, d_wsgu_t);  float* wsguT= (float*)p;
    cudaGetSymbolAddress(&p, d_wsd_t);   float* wsdT = (float*)p;
    cudaGetSymbolAddress(&p, d_acts);    float* acts = (float*)p;
    cudaGetSymbolAddress(&p, d_acte);    float* acte = (float*)p;

    cudaFuncSetAttribute(mma_gemm<false, false>, cudaFuncAttributeMaxDynamicSharedMemorySize, GSMEM_BYTES);
    cudaFuncSetAttribute(mma_gemm<true,  true >, cudaFuncAttributeMaxDynamicSharedMemorySize, GSMEM_BYTES);
    cudaFuncSetAttribute(mma_gemm<false, true >, cudaFuncAttributeMaxDynamicSharedMemorySize, GSMEM_BYTES);

    // --- prep: tf32 rounding + fast weight transposes to [N][K] ---
    round_x_kernel<<<(T_TOK * DIM / 4) / 256, 256>>>(x, xt);
    transpose_tf32_v2<<<dim3((2 * NI) / 64, DIM / 64, NE), 256>>>(
        wgu, (long long)DIM * 2 * NI, wguT, (long long)(2 * NI) * DIM, DIM, 2 * NI, NI);
    transpose_tf32_v2<<<dim3(DIM / 64, NI / 64, NE), 256>>>(
        wdn, (long long)NI * DIM, wdnT, (long long)DIM * NI, NI, DIM, 0);
    transpose_tf32_v2<<<dim3((2 * SIH) / 64, DIM / 64, 1), 256>>>(
        wsgu, 0, wsguT, 0, DIM, 2 * SIH, SIH);
    transpose_tf32_v2<<<dim3(DIM / 64, SIH / 64, 1), 256>>>(
        wsd, 0, wsdT, 0, SIH, DIM, 0);

    // --- router + routing tables ---
    router_kernel<<<T_TOK, 128>>>(x, gw, gb, ti, tw);
    routing_build<<<NE, 256>>>(ti, tok, pos, cnt);

    // --- shared expert: act = swiglu(x @ wsgu)  [2048 x 2048], fused epilogue ---
    mma_gemm<false, true><<<dim3((2 * SIH) / 128, T_TOK / 128, 1), 256, GSMEM_BYTES>>>(
        xt, 0, DIM, wsguT, 0, DIM, acts, 0, SIH,
        (const int*)0, T_TOK, DIM / 32, (const int*)0);
    // out = act @ wsd  [2048 x 2048] (full store initializes out)
    mma_gemm<false, false><<<dim3(DIM / 128, T_TOK / 128, 1), 256, GSMEM_BYTES>>>(
        acts, 0, SIH, wsdT, 0, SIH, out, 0, DIM,
        (const int*)0, T_TOK, SIH / 32, (const int*)0);

    // --- routed experts: act[e] = swiglu(gather(x) @ wgu[e]), fused epilogue ---
    mma_gemm<true, true><<<dim3((2 * NI) / 128, CAP / 128, NE), 256, GSMEM_BYTES>>>(
        xt, 0, DIM, wguT, (long long)(2 * NI) * DIM, DIM,
        acte, (long long)CAP * NI, NI,
        cnt, 0, DIM / 32, tok);
    // y[e] = act[e] @ wdn[e]  (dense store into gu scratch reused as y)
    mma_gemm<false, false><<<dim3(DIM / 128, CAP / 128, NE), 256, GSMEM_BYTES>>>(
        acte, (long long)CAP * NI, NI, wdnT, (long long)DIM * NI, NI,
        gu, (long long)CAP * DIM, DIM,
        cnt, 0, NI / 32, (const int*)0);
    combine_kernel<<<T_TOK * 2, 256>>>(gu, ti, pos, tw, out);
}